// round 1
// baseline (speedup 1.0000x reference)
#include <cuda_runtime.h>
#include <cstdint>

// Problem constants
#define NROWS 65536      // 64 * 1024 flattened rows
#define DIM   256        // embedding dim
#define KCODE 1024       // num codes
#define ND    (NROWS * DIM)

// GEMM tiling
#define BM 128           // rows per CTA
#define BN 128           // codes per tile (K loop inside CTA: 8 tiles)
#define NT 256           // threads per CTA
#define TM 8
#define TN 8
#define CHUNK 16         // d-depth per smem B chunk

// Scratch (no device mallocs allowed -> __device__ globals)
__device__ __align__(16) float g_ne[KCODE];       // ||e_c||^2
__device__ int   g_idx[NROWS];                    // argmin indices
__device__ float g_part[16384];                   // per-block loss partials

// ---------------------------------------------------------------------------
// Kernel 0: codebook squared norms.  Unfused mul+add to mimic reference
// (jnp computes emb*emb then sum).
// ---------------------------------------------------------------------------
__global__ void k_ne(const float* __restrict__ emb) {
    int c = blockIdx.x * blockDim.x + threadIdx.x;
    if (c < KCODE) {
        const float* e = emb + (size_t)c * DIM;
        float s = 0.0f;
        #pragma unroll 8
        for (int d = 0; d < DIM; d++) s = __fadd_rn(s, __fmul_rn(e[d], e[d]));
        g_ne[c] = s;
    }
}

// ---------------------------------------------------------------------------
// Kernel 1: distances + argmin.  One CTA = 128 rows x all 1024 codes.
// A panel resident in smem (transposed [d][row], XOR-swizzled), B streamed in
// double-buffered 16x128 chunks.  8x8 register micro-tiles.
// Distance replicates reference rounding: fl(fl(nx+ne) - fl(2*dot)).
// ---------------------------------------------------------------------------
#define SMEM_A_FLOATS (DIM * BM)                 // 32768
#define SMEM_B_FLOATS (2 * CHUNK * BN)           // 4096
#define SMEM_TOTAL_FLOATS (SMEM_A_FLOATS + SMEM_B_FLOATS + BM)
#define SMEM_BYTES (SMEM_TOTAL_FLOATS * 4)       // 147968 B

__global__ __launch_bounds__(NT, 1)
void k_argmin(const float* __restrict__ x, const float* __restrict__ emb,
              float* __restrict__ out, int idx_off) {
    extern __shared__ float sm[];
    float* As   = sm;                          // [256][128] swizzled
    float* Bs   = sm + SMEM_A_FLOATS;          // 2 x [16][128] swizzled
    float* s_nx = Bs + SMEM_B_FLOATS;          // [128]

    const int tid   = threadIdx.x;
    const int tx    = tid & 15;                // code dim
    const int ty    = tid >> 4;                // row dim
    const int rbase = blockIdx.x * BM;

    // --- load A panel, transpose + swizzle.  Swizzle: row ^ (((d>>2)&3)<<3).
    for (int i = tid; i < BM * (DIM / 4); i += NT) {
        int r  = i >> 6;          // row 0..127
        int c4 = i & 63;          // float4 col
        float4 v = reinterpret_cast<const float4*>(x)[(size_t)(rbase + r) * (DIM / 4) + c4];
        int d0 = c4 << 2;
        float vv[4] = {v.x, v.y, v.z, v.w};
        #pragma unroll
        for (int k = 0; k < 4; k++) {
            int d  = d0 + k;
            int sw = ((d >> 2) & 3) << 3;
            As[d * BM + (r ^ sw)] = vv[k];
        }
    }
    __syncthreads();

    // --- nx per row (sequential fp32, unfused mul+add)
    if (tid < BM) {
        float s = 0.0f;
        #pragma unroll 8
        for (int d = 0; d < DIM; d++) {
            int sw = ((d >> 2) & 3) << 3;
            float v = As[d * BM + (tid ^ sw)];
            s = __fadd_rn(s, __fmul_rn(v, v));
        }
        s_nx[tid] = s;
    }
    __syncthreads();

    float bestv[TM];
    int   besti[TM];
    #pragma unroll
    for (int i = 0; i < TM; i++) { bestv[i] = 3.4e38f; besti[i] = 0; }

    const float4* bp = reinterpret_cast<const float4*>(emb);
    const int cl  = tid >> 2;            // code-local 0..63
    const int dd0 = (tid & 3) << 2;      // d offset within chunk
    const int swS = (tid & 3) << 3;      // store swizzle (constant per thread)

    for (int ct = 0; ct < KCODE / BN; ct++) {
        float acc[TM][TN];
        #pragma unroll
        for (int i = 0; i < TM; i++)
            #pragma unroll
            for (int j = 0; j < TN; j++) acc[i][j] = 0.0f;

        // prefetch chunk 0
        int gbase = (ct * BN + cl) * (DIM / 4) + (tid & 3);
        float4 p0 = bp[gbase];
        float4 p1 = bp[gbase + 64 * (DIM / 4)];

        int buf = 0;
        for (int dc = 0; dc < DIM / CHUNK; dc++) {
            // store chunk dc (conflict-free thanks to swizzle)
            float* Bb = Bs + buf * (CHUNK * BN);
            int col0 = cl ^ swS;
            int col1 = (cl + 64) ^ swS;
            Bb[(dd0 + 0) * BN + col0] = p0.x;
            Bb[(dd0 + 1) * BN + col0] = p0.y;
            Bb[(dd0 + 2) * BN + col0] = p0.z;
            Bb[(dd0 + 3) * BN + col0] = p0.w;
            Bb[(dd0 + 0) * BN + col1] = p1.x;
            Bb[(dd0 + 1) * BN + col1] = p1.y;
            Bb[(dd0 + 2) * BN + col1] = p1.z;
            Bb[(dd0 + 3) * BN + col1] = p1.w;
            __syncthreads();

            if (dc < DIM / CHUNK - 1) {
                int gb = (ct * BN + cl) * (DIM / 4) + (dc + 1) * 4 + (tid & 3);
                p0 = bp[gb];
                p1 = bp[gb + 64 * (DIM / 4)];
            }

            // compute on chunk dc
            #pragma unroll
            for (int dd = 0; dd < CHUNK; dd++) {
                int d  = dc * CHUNK + dd;
                int sw = ((dd >> 2) & 3) << 3;   // == ((d>>2)&3)<<3
                const float4* ap = reinterpret_cast<const float4*>(&As[d * BM + ((ty * 8) ^ sw)]);
                float4 a0 = ap[0], a1 = ap[1];
                const float4* bq = reinterpret_cast<const float4*>(&Bb[dd * BN + ((tx * 8) ^ sw)]);
                float4 b0 = bq[0], b1 = bq[1];
                float av[8] = {a0.x, a0.y, a0.z, a0.w, a1.x, a1.y, a1.z, a1.w};
                float bv[8] = {b0.x, b0.y, b0.z, b0.w, b1.x, b1.y, b1.z, b1.w};
                #pragma unroll
                for (int i = 0; i < TM; i++)
                    #pragma unroll
                    for (int j = 0; j < TN; j++)
                        acc[i][j] = fmaf(av[i], bv[j], acc[i][j]);
            }
            buf ^= 1;
        }

        // epilogue: distance + running argmin (codes ascending -> strict '<'
        // keeps lowest index on ties, matching jnp argmin)
        const float4* nep = reinterpret_cast<const float4*>(&g_ne[ct * BN + tx * 8]);
        float4 n0 = nep[0], n1 = nep[1];
        float nev[8] = {n0.x, n0.y, n0.z, n0.w, n1.x, n1.y, n1.z, n1.w};
        #pragma unroll
        for (int i = 0; i < TM; i++) {
            float nx = s_nx[ty * 8 + i];
            #pragma unroll
            for (int j = 0; j < TN; j++) {
                float t    = __fadd_rn(nx, nev[j]);
                float dist = __fadd_rn(t, __fmul_rn(-2.0f, acc[i][j]));
                if (dist < bestv[i]) { bestv[i] = dist; besti[i] = ct * BN + tx * 8 + j; }
            }
        }
    }

    // cross-tx lexicographic (val, idx) min within each 16-lane half
    #pragma unroll
    for (int off = 8; off >= 1; off >>= 1) {
        #pragma unroll
        for (int i = 0; i < TM; i++) {
            float ov = __shfl_xor_sync(0xffffffffu, bestv[i], off);
            int   oi = __shfl_xor_sync(0xffffffffu, besti[i], off);
            if (ov < bestv[i] || (ov == bestv[i] && oi < besti[i])) {
                bestv[i] = ov; besti[i] = oi;
            }
        }
    }
    if (tx == 0) {
        #pragma unroll
        for (int i = 0; i < TM; i++) {
            int r = rbase + ty * 8 + i;
            g_idx[r] = besti[i];
            if (idx_off >= 0) out[idx_off + r] = (float)besti[i];
        }
    }
}

// ---------------------------------------------------------------------------
// Kernel 2: gather + straight-through output + deterministic loss partials.
// out = fl(x + fl(q - x))  (replicates reference STE rounding).
// ---------------------------------------------------------------------------
__global__ __launch_bounds__(256)
void k_quant(const float* __restrict__ x, const float* __restrict__ emb,
             float* __restrict__ out) {
    int g   = blockIdx.x * 256 + threadIdx.x;   // float4 index, 4194304 total
    int row = g >> 6;
    int c4  = g & 63;
    int idx = g_idx[row];
    float4 q  = reinterpret_cast<const float4*>(emb)[idx * (DIM / 4) + c4];
    float4 xv = reinterpret_cast<const float4*>(x)[g];
    float4 t, o;
    t.x = __fadd_rn(q.x, -xv.x); t.y = __fadd_rn(q.y, -xv.y);
    t.z = __fadd_rn(q.z, -xv.z); t.w = __fadd_rn(q.w, -xv.w);
    o.x = __fadd_rn(xv.x, t.x);  o.y = __fadd_rn(xv.y, t.y);
    o.z = __fadd_rn(xv.z, t.z);  o.w = __fadd_rn(xv.w, t.w);
    reinterpret_cast<float4*>(out)[g] = o;

    float s = t.x * t.x + t.y * t.y + t.z * t.z + t.w * t.w;
    #pragma unroll
    for (int off = 16; off >= 1; off >>= 1)
        s += __shfl_down_sync(0xffffffffu, s, off);
    __shared__ float wsum[8];
    int lane = threadIdx.x & 31, warp = threadIdx.x >> 5;
    if (lane == 0) wsum[warp] = s;
    __syncthreads();
    if (threadIdx.x == 0) {
        float tsum = wsum[0];
        #pragma unroll
        for (int w = 1; w < 8; w++) tsum += wsum[w];
        g_part[blockIdx.x] = tsum;
    }
}

// ---------------------------------------------------------------------------
// Kernel 3: deterministic final loss reduction (fixed order).
// ---------------------------------------------------------------------------
__global__ void k_loss(float* __restrict__ out_loss) {
    __shared__ float smr[256];
    int tid = threadIdx.x;
    float s = 0.0f;
    for (int i = tid; i < 16384; i += 256) s += g_part[i];
    smr[tid] = s;
    __syncthreads();
    for (int off = 128; off >= 1; off >>= 1) {
        if (tid < off) smr[tid] += smr[tid + off];
        __syncthreads();
    }
    if (tid == 0) *out_loss = 0.25f * (smr[0] / 16777216.0f);
}

// ---------------------------------------------------------------------------
extern "C" void kernel_launch(void* const* d_in, const int* in_sizes, int n_in,
                              void* d_out, int out_size) {
    const float* x   = (const float*)d_in[0];
    const float* emb = (const float*)d_in[1];
    if (n_in >= 2 && in_sizes[0] == KCODE * DIM && in_sizes[1] == NROWS * DIM) {
        const float* t = x; x = emb; emb = t;   // defensive: swap if order flipped
    }
    float* out = (float*)d_out;

    // output layout: tuple (quantized[ND], loss[1], indices[NROWS]) concatenated
    int loss_off = -1, idx_off = -1;
    if (out_size >= ND + 1 + NROWS)      { loss_off = ND; idx_off = ND + 1; }
    else if (out_size == ND + NROWS)     { idx_off = ND; }
    else if (out_size == ND + 1)         { loss_off = ND; }

    cudaFuncSetAttribute(k_argmin, cudaFuncAttributeMaxDynamicSharedMemorySize, SMEM_BYTES);

    k_ne<<<(KCODE + 255) / 256, 256>>>(emb);
    k_argmin<<<NROWS / BM, NT, SMEM_BYTES>>>(x, emb, out, idx_off);
    k_quant<<<ND / 4 / 256, 256>>>(x, emb, out);
    if (loss_off >= 0) k_loss<<<1, 256>>>(out + loss_off);
}